// round 2
// baseline (speedup 1.0000x reference)
#include <cuda_runtime.h>
#include <cuda_bf16.h>
#include <cstdint>

#define S_LEN 2048
#define BATCH 2
#define EMB 2048
#define NH 32
#define NKV 8
#define HD 64
#define WIN 128
#define MSEQ 4096   // B*S rows

// ---------------- scratch (static device globals; no allocation allowed) ----
__device__ float g_Q[MSEQ * NH * HD];     // 32 MB
__device__ float g_K[MSEQ * NKV * HD];    // 8 MB
__device__ float g_V[MSEQ * NKV * HD];    // 8 MB
__device__ float g_ctx[MSEQ * NH * HD];   // 32 MB

// ---------------- SGEMM: C[M,N] = A[M,K] * B[N,K]^T + bias[N] ---------------
// BM=BN=128, BK=16, 256 threads, 8x8 per-thread tile, smem double-buffered.
__global__ __launch_bounds__(256) void sgemm_nt(
    const float* __restrict__ A, const float* __restrict__ B,
    const float* __restrict__ bias, float* __restrict__ C,
    int M, int N, int K)
{
    __shared__ float As[2][16][128];
    __shared__ float Bs[2][16][128];

    const int tid = threadIdx.x;
    const int m0 = blockIdx.y * 128;
    const int n0 = blockIdx.x * 128;
    const int tm = (tid >> 4) << 3;   // 0..120
    const int tn = (tid & 15) << 3;   // 0..120

    float acc[8][8];
#pragma unroll
    for (int i = 0; i < 8; i++)
#pragma unroll
        for (int j = 0; j < 8; j++) acc[i][j] = 0.f;

    float4 ra[2], rb[2];

    auto loadG = [&](int k0) {
#pragma unroll
        for (int it = 0; it < 2; it++) {
            int l = tid + it * 256;      // 0..511
            int row = l >> 2;            // 0..127
            int kq = (l & 3) << 2;       // 0,4,8,12
            ra[it] = *(const float4*)&A[(size_t)(m0 + row) * K + k0 + kq];
            rb[it] = *(const float4*)&B[(size_t)(n0 + row) * K + k0 + kq];
        }
    };
    auto storeS = [&](int buf) {
#pragma unroll
        for (int it = 0; it < 2; it++) {
            int l = tid + it * 256;
            int row = l >> 2;
            int kq = (l & 3) << 2;
            As[buf][kq + 0][row] = ra[it].x;
            As[buf][kq + 1][row] = ra[it].y;
            As[buf][kq + 2][row] = ra[it].z;
            As[buf][kq + 3][row] = ra[it].w;
            Bs[buf][kq + 0][row] = rb[it].x;
            Bs[buf][kq + 1][row] = rb[it].y;
            Bs[buf][kq + 2][row] = rb[it].z;
            Bs[buf][kq + 3][row] = rb[it].w;
        }
    };

    loadG(0);
    storeS(0);
    __syncthreads();

    const int nch = K >> 4;
    int buf = 0;
    for (int ci = 0; ci < nch; ci++) {
        if (ci + 1 < nch) loadG((ci + 1) << 4);
#pragma unroll
        for (int kk = 0; kk < 16; kk++) {
            float a[8], b[8];
            *(float4*)&a[0] = *(float4*)&As[buf][kk][tm];
            *(float4*)&a[4] = *(float4*)&As[buf][kk][tm + 4];
            *(float4*)&b[0] = *(float4*)&Bs[buf][kk][tn];
            *(float4*)&b[4] = *(float4*)&Bs[buf][kk][tn + 4];
#pragma unroll
            for (int i = 0; i < 8; i++)
#pragma unroll
                for (int j = 0; j < 8; j++) acc[i][j] += a[i] * b[j];
        }
        if (ci + 1 < nch) storeS(buf ^ 1);
        __syncthreads();
        buf ^= 1;
    }

#pragma unroll
    for (int i = 0; i < 8; i++) {
        size_t rowoff = (size_t)(m0 + tm + i) * N + n0 + tn;
#pragma unroll
        for (int j = 0; j < 8; j += 4) {
            float4 o;
            o.x = acc[i][j + 0] + bias[n0 + tn + j + 0];
            o.y = acc[i][j + 1] + bias[n0 + tn + j + 1];
            o.z = acc[i][j + 2] + bias[n0 + tn + j + 2];
            o.w = acc[i][j + 3] + bias[n0 + tn + j + 3];
            *(float4*)&C[rowoff + j] = o;
        }
    }
}

// ---------------- YaRN RoPE (in-place), one thread per (bs, head, pair) -----
__global__ void rope_kernel(float* __restrict__ X, const int* __restrict__ pos_ids,
                            int BS, int H)
{
    int idx = blockIdx.x * blockDim.x + threadIdx.x;
    int total = BS * H * (HD / 2);
    if (idx >= total) return;
    int i = idx & 31;                 // pair index 0..31
    int h = (idx >> 5) % H;
    int bs = idx / (32 * H);

    float pos = (float)pos_ids[bs];

    // freqs = base^(-2i/HD); YaRN ramp
    float freq = expf(-((float)(2 * i) * (1.0f / 64.0f)) * 9.210340371976184f); // ln(1e4)
    float wl = 6.283185307179586f / freq;
    float t = (wl - 32.0f) * (1.0f / 992.0f);          // (wl-low)/(high-low)
    t = fminf(fmaxf(t, 0.0f), 1.0f);
    float eff = freq * (1.0f - t) + freq * 0.25f * t;  // scale = 4
    float ang = pos * eff * 1.1386294361119891f;       // 0.1*ln(4)+1
    float s, c;
    sincosf(ang, &s, &c);

    float* p = X + ((size_t)bs * H + h) * HD;
    float x1 = p[i];
    float x2 = p[i + 32];
    p[i] = x1 * c - x2 * s;
    p[i + 32] = x2 * c + x1 * s;
}

// ---------------- sliding-window attention with sink ------------------------
// grid: (qt=32, h=32, b=2), 128 threads.
// Each block: 64 queries of one (b, q-head). Key tiles of 64 (<=3 per block).
// Thread t: row r = t>>1, key-half = t&1 (32 keys per thread per tile);
// per-thread online softmax, pair-merge + sink in epilogue via shfl.
__global__ __launch_bounds__(128) void attn_kernel(
    const float* __restrict__ Q, const float* __restrict__ K,
    const float* __restrict__ V, const float* __restrict__ sinks,
    float* __restrict__ ctx)
{
    __shared__ float Qs[64][HD];
    __shared__ float Ks[64][HD];
    __shared__ float Vs[64][HD];

    const int b = blockIdx.z;
    const int h = blockIdx.y;
    const int q0 = blockIdx.x * 64;
    const int kvh = h >> 2;            // GS = 4
    const int tid = threadIdx.x;
    const int r = tid >> 1;
    const int half = tid & 1;
    const int i_glob = q0 + r;

    // load Q tile (64x64 fp32 = 1024 float4, 8 per thread)
#pragma unroll
    for (int it = 0; it < 8; it++) {
        int l = tid + it * 128;
        int row = l >> 4;
        int dd = (l & 15) << 2;
        *(float4*)&Qs[row][dd] =
            *(const float4*)&Q[(((size_t)(b * S_LEN + q0 + row)) * NH + h) * HD + dd];
    }

    float m = -1e30f, lsum = 0.f;
    float acc[HD];
#pragma unroll
    for (int d = 0; d < HD; d++) acc[d] = 0.f;

    const int kt_begin = (q0 >= WIN) ? (q0 - WIN) : 0;
    for (int kts = kt_begin; kts <= q0; kts += 64) {
        __syncthreads();
#pragma unroll
        for (int it = 0; it < 8; it++) {
            int l = tid + it * 128;
            int row = l >> 4;
            int dd = (l & 15) << 2;
            size_t g = (((size_t)(b * S_LEN + kts + row)) * NKV + kvh) * HD + dd;
            *(float4*)&Ks[row][dd] = *(const float4*)&K[g];
            *(float4*)&Vs[row][dd] = *(const float4*)&V[g];
        }
        __syncthreads();

        // scores for my 32 keys
        float sc[32];
#pragma unroll
        for (int c = 0; c < 32; c++) sc[c] = 0.f;
#pragma unroll
        for (int dc = 0; dc < HD; dc += 8) {
            float4 qa = *(float4*)&Qs[r][dc];
            float4 qb = *(float4*)&Qs[r][dc + 4];
#pragma unroll
            for (int c = 0; c < 32; c++) {
                const float* kp = &Ks[half * 32 + c][dc];
                float4 ka = *(const float4*)kp;
                float4 kb = *(const float4*)(kp + 4);
                sc[c] += qa.x * ka.x + qa.y * ka.y + qa.z * ka.z + qa.w * ka.w
                       + qb.x * kb.x + qb.y * kb.y + qb.z * kb.z + qb.w * kb.w;
            }
        }

        // mask + scale + tile max
        float tmax = -1e30f;
#pragma unroll
        for (int c = 0; c < 32; c++) {
            int j = kts + half * 32 + c;
            bool ok = (j <= i_glob) && (j > i_glob - WIN);
            sc[c] = ok ? sc[c] * 0.125f : -1e30f;
            tmax = fmaxf(tmax, sc[c]);
        }
        float m_new = fmaxf(m, tmax);
        if (m_new > -1e29f) {
            float corr = __expf(m - m_new);   // m=-1e30 -> 0
            lsum *= corr;
#pragma unroll
            for (int d = 0; d < HD; d++) acc[d] *= corr;
#pragma unroll
            for (int c = 0; c < 32; c++) {
                float p = __expf(sc[c] - m_new);   // masked -> exp(-huge) = 0
                lsum += p;
                const float* vp = &Vs[half * 32 + c][0];
#pragma unroll
                for (int d = 0; d < HD; d += 4) {
                    float4 v = *(const float4*)(vp + d);
                    acc[d + 0] += p * v.x;
                    acc[d + 1] += p * v.y;
                    acc[d + 2] += p * v.z;
                    acc[d + 3] += p * v.w;
                }
            }
            m = m_new;
        }
    }

    // merge the two key-half threads + sink
    float m_o = __shfl_xor_sync(0xffffffffu, m, 1);
    float l_o = __shfl_xor_sync(0xffffffffu, lsum, 1);
    float snk = sinks[h];
    float m_f = fmaxf(fmaxf(m, m_o), snk);
    float se = __expf(m - m_f);
    float l_f = lsum * se + l_o * __expf(m_o - m_f) + __expf(snk - m_f);
    float inv = 1.0f / l_f;

    size_t base = (((size_t)(b * S_LEN + i_glob)) * NH + h) * HD;
#pragma unroll
    for (int d = 0; d < HD; d++) {
        float a = acc[d] * se;
        a += __shfl_xor_sync(0xffffffffu, a, 1);
        acc[d] = a * inv;
    }
    // both threads of the pair hold identical results; split the store
#pragma unroll
    for (int d = half * 32; d < half * 32 + 32; d += 4) {
        *(float4*)&ctx[base + d] =
            make_float4(acc[d], acc[d + 1], acc[d + 2], acc[d + 3]);
    }
}

// ---------------- launch -----------------------------------------------------
extern "C" void kernel_launch(void* const* d_in, const int* in_sizes, int n_in,
                              void* d_out, int out_size)
{
    const float* x     = (const float*)d_in[0];
    const float* Wq    = (const float*)d_in[1];
    const float* bq    = (const float*)d_in[2];
    const float* Wk    = (const float*)d_in[3];
    const float* bk    = (const float*)d_in[4];
    const float* Wv    = (const float*)d_in[5];
    const float* bv    = (const float*)d_in[6];
    const float* Wo    = (const float*)d_in[7];
    const float* bo    = (const float*)d_in[8];
    const float* sinks = (const float*)d_in[9];
    const int*   pos   = (const int*)d_in[10];
    float* out = (float*)d_out;

    float *gQ, *gK, *gV, *gctx;
    cudaGetSymbolAddress((void**)&gQ, g_Q);
    cudaGetSymbolAddress((void**)&gK, g_K);
    cudaGetSymbolAddress((void**)&gV, g_V);
    cudaGetSymbolAddress((void**)&gctx, g_ctx);

    // projections
    sgemm_nt<<<dim3(16, 32), 256>>>(x, Wq, bq, gQ, MSEQ, NH * HD, EMB);
    sgemm_nt<<<dim3(4, 32), 256>>>(x, Wk, bk, gK, MSEQ, NKV * HD, EMB);
    sgemm_nt<<<dim3(4, 32), 256>>>(x, Wv, bv, gV, MSEQ, NKV * HD, EMB);

    // RoPE on Q and K
    rope_kernel<<<(MSEQ * NH * 32 + 255) / 256, 256>>>(gQ, pos, MSEQ, NH);
    rope_kernel<<<(MSEQ * NKV * 32 + 255) / 256, 256>>>(gK, pos, MSEQ, NKV);

    // windowed attention with sink
    attn_kernel<<<dim3(S_LEN / 64, NH, BATCH), 128>>>(gQ, gK, gV, sinks, gctx);

    // output projection
    sgemm_nt<<<dim3(16, 32), 256>>>(gctx, Wo, bo, out, MSEQ, EMB, EMB);
}

// round 6
// speedup vs baseline: 1.0004x; 1.0004x over previous
#include <cuda_runtime.h>
#include <cuda_bf16.h>
#include <cstdint>

#define S_LEN 2048
#define BATCH 2
#define EMB 2048
#define NH 32
#define NKV 8
#define HD 64
#define WIN 128
#define MSEQ 4096   // B*S rows

// ---------------- scratch (static device globals; no allocation allowed) ----
__device__ float g_Q[MSEQ * NH * HD];     // 32 MB
__device__ float g_K[MSEQ * NKV * HD];    // 8 MB
__device__ float g_V[MSEQ * NKV * HD];    // 8 MB
__device__ float g_ctx[MSEQ * NH * HD];   // 32 MB

// ---------------- SGEMM: C[M,N] = A[M,K] * B[N,K]^T + bias[N] ---------------
// BM=BN=128, BK=16, 256 threads, 8x8 per-thread tile, smem double-buffered.
__global__ __launch_bounds__(256) void sgemm_nt(
    const float* __restrict__ A, const float* __restrict__ B,
    const float* __restrict__ bias, float* __restrict__ C,
    int M, int N, int K)
{
    __shared__ float As[2][16][128];
    __shared__ float Bs[2][16][128];

    const int tid = threadIdx.x;
    const int m0 = blockIdx.y * 128;
    const int n0 = blockIdx.x * 128;
    const int tm = (tid >> 4) << 3;   // 0..120
    const int tn = (tid & 15) << 3;   // 0..120

    float acc[8][8];
#pragma unroll
    for (int i = 0; i < 8; i++)
#pragma unroll
        for (int j = 0; j < 8; j++) acc[i][j] = 0.f;

    float4 ra[2], rb[2];

    auto loadG = [&](int k0) {
#pragma unroll
        for (int it = 0; it < 2; it++) {
            int l = tid + it * 256;      // 0..511
            int row = l >> 2;            // 0..127
            int kq = (l & 3) << 2;       // 0,4,8,12
            ra[it] = *(const float4*)&A[(size_t)(m0 + row) * K + k0 + kq];
            rb[it] = *(const float4*)&B[(size_t)(n0 + row) * K + k0 + kq];
        }
    };
    auto storeS = [&](int buf) {
#pragma unroll
        for (int it = 0; it < 2; it++) {
            int l = tid + it * 256;
            int row = l >> 2;
            int kq = (l & 3) << 2;
            As[buf][kq + 0][row] = ra[it].x;
            As[buf][kq + 1][row] = ra[it].y;
            As[buf][kq + 2][row] = ra[it].z;
            As[buf][kq + 3][row] = ra[it].w;
            Bs[buf][kq + 0][row] = rb[it].x;
            Bs[buf][kq + 1][row] = rb[it].y;
            Bs[buf][kq + 2][row] = rb[it].z;
            Bs[buf][kq + 3][row] = rb[it].w;
        }
    };

    loadG(0);
    storeS(0);
    __syncthreads();

    const int nch = K >> 4;
    int buf = 0;
    for (int ci = 0; ci < nch; ci++) {
        if (ci + 1 < nch) loadG((ci + 1) << 4);
#pragma unroll
        for (int kk = 0; kk < 16; kk++) {
            float a[8], b[8];
            *(float4*)&a[0] = *(float4*)&As[buf][kk][tm];
            *(float4*)&a[4] = *(float4*)&As[buf][kk][tm + 4];
            *(float4*)&b[0] = *(float4*)&Bs[buf][kk][tn];
            *(float4*)&b[4] = *(float4*)&Bs[buf][kk][tn + 4];
#pragma unroll
            for (int i = 0; i < 8; i++)
#pragma unroll
                for (int j = 0; j < 8; j++) acc[i][j] += a[i] * b[j];
        }
        if (ci + 1 < nch) storeS(buf ^ 1);
        __syncthreads();
        buf ^= 1;
    }

#pragma unroll
    for (int i = 0; i < 8; i++) {
        size_t rowoff = (size_t)(m0 + tm + i) * N + n0 + tn;
#pragma unroll
        for (int j = 0; j < 8; j += 4) {
            float4 o;
            o.x = acc[i][j + 0] + bias[n0 + tn + j + 0];
            o.y = acc[i][j + 1] + bias[n0 + tn + j + 1];
            o.z = acc[i][j + 2] + bias[n0 + tn + j + 2];
            o.w = acc[i][j + 3] + bias[n0 + tn + j + 3];
            *(float4*)&C[rowoff + j] = o;
        }
    }
}

// ---------------- YaRN RoPE (in-place), one thread per (bs, head, pair) -----
__global__ void rope_kernel(float* __restrict__ X, const int* __restrict__ pos_ids,
                            int BS, int H)
{
    int idx = blockIdx.x * blockDim.x + threadIdx.x;
    int total = BS * H * (HD / 2);
    if (idx >= total) return;
    int i = idx & 31;                 // pair index 0..31
    int h = (idx >> 5) % H;
    int bs = idx / (32 * H);

    float pos = (float)pos_ids[bs];

    // freqs = base^(-2i/HD); YaRN ramp
    float freq = expf(-((float)(2 * i) * (1.0f / 64.0f)) * 9.210340371976184f); // ln(1e4)
    float wl = 6.283185307179586f / freq;
    float t = (wl - 32.0f) * (1.0f / 992.0f);          // (wl-low)/(high-low)
    t = fminf(fmaxf(t, 0.0f), 1.0f);
    float eff = freq * (1.0f - t) + freq * 0.25f * t;  // scale = 4
    float ang = pos * eff * 1.1386294361119891f;       // 0.1*ln(4)+1
    float s, c;
    sincosf(ang, &s, &c);

    float* p = X + ((size_t)bs * H + h) * HD;
    float x1 = p[i];
    float x2 = p[i + 32];
    p[i] = x1 * c - x2 * s;
    p[i + 32] = x2 * c + x1 * s;
}

// ---------------- sliding-window attention with sink ------------------------
// grid: (qt=32, h=32, b=2), 128 threads.
// Each block: 64 queries of one (b, q-head). Key tiles of 64 (<=3 per block).
// Thread t: row r = t>>1, key-half = t&1 (32 keys per thread per tile);
// per-thread online softmax, pair-merge + sink in epilogue via shfl.
__global__ __launch_bounds__(128) void attn_kernel(
    const float* __restrict__ Q, const float* __restrict__ K,
    const float* __restrict__ V, const float* __restrict__ sinks,
    float* __restrict__ ctx)
{
    __shared__ float Qs[64][HD];
    __shared__ float Ks[64][HD];
    __shared__ float Vs[64][HD];

    const int b = blockIdx.z;
    const int h = blockIdx.y;
    const int q0 = blockIdx.x * 64;
    const int kvh = h >> 2;            // GS = 4
    const int tid = threadIdx.x;
    const int r = tid >> 1;
    const int half = tid & 1;
    const int i_glob = q0 + r;

    // load Q tile (64x64 fp32 = 1024 float4, 8 per thread)
#pragma unroll
    for (int it = 0; it < 8; it++) {
        int l = tid + it * 128;
        int row = l >> 4;
        int dd = (l & 15) << 2;
        *(float4*)&Qs[row][dd] =
            *(const float4*)&Q[(((size_t)(b * S_LEN + q0 + row)) * NH + h) * HD + dd];
    }

    float m = -1e30f, lsum = 0.f;
    float acc[HD];
#pragma unroll
    for (int d = 0; d < HD; d++) acc[d] = 0.f;

    const int kt_begin = (q0 >= WIN) ? (q0 - WIN) : 0;
    for (int kts = kt_begin; kts <= q0; kts += 64) {
        __syncthreads();
#pragma unroll
        for (int it = 0; it < 8; it++) {
            int l = tid + it * 128;
            int row = l >> 4;
            int dd = (l & 15) << 2;
            size_t g = (((size_t)(b * S_LEN + kts + row)) * NKV + kvh) * HD + dd;
            *(float4*)&Ks[row][dd] = *(const float4*)&K[g];
            *(float4*)&Vs[row][dd] = *(const float4*)&V[g];
        }
        __syncthreads();

        // scores for my 32 keys
        float sc[32];
#pragma unroll
        for (int c = 0; c < 32; c++) sc[c] = 0.f;
#pragma unroll
        for (int dc = 0; dc < HD; dc += 8) {
            float4 qa = *(float4*)&Qs[r][dc];
            float4 qb = *(float4*)&Qs[r][dc + 4];
#pragma unroll
            for (int c = 0; c < 32; c++) {
                const float* kp = &Ks[half * 32 + c][dc];
                float4 ka = *(const float4*)kp;
                float4 kb = *(const float4*)(kp + 4);
                sc[c] += qa.x * ka.x + qa.y * ka.y + qa.z * ka.z + qa.w * ka.w
                       + qb.x * kb.x + qb.y * kb.y + qb.z * kb.z + qb.w * kb.w;
            }
        }

        // mask + scale + tile max
        float tmax = -1e30f;
#pragma unroll
        for (int c = 0; c < 32; c++) {
            int j = kts + half * 32 + c;
            bool ok = (j <= i_glob) && (j > i_glob - WIN);
            sc[c] = ok ? sc[c] * 0.125f : -1e30f;
            tmax = fmaxf(tmax, sc[c]);
        }
        float m_new = fmaxf(m, tmax);
        if (m_new > -1e29f) {
            float corr = __expf(m - m_new);   // m=-1e30 -> 0
            lsum *= corr;
#pragma unroll
            for (int d = 0; d < HD; d++) acc[d] *= corr;
#pragma unroll
            for (int c = 0; c < 32; c++) {
                float p = __expf(sc[c] - m_new);   // masked -> exp(-huge) = 0
                lsum += p;
                const float* vp = &Vs[half * 32 + c][0];
#pragma unroll
                for (int d = 0; d < HD; d += 4) {
                    float4 v = *(const float4*)(vp + d);
                    acc[d + 0] += p * v.x;
                    acc[d + 1] += p * v.y;
                    acc[d + 2] += p * v.z;
                    acc[d + 3] += p * v.w;
                }
            }
            m = m_new;
        }
    }

    // merge the two key-half threads + sink
    float m_o = __shfl_xor_sync(0xffffffffu, m, 1);
    float l_o = __shfl_xor_sync(0xffffffffu, lsum, 1);
    float snk = sinks[h];
    float m_f = fmaxf(fmaxf(m, m_o), snk);
    float se = __expf(m - m_f);
    float l_f = lsum * se + l_o * __expf(m_o - m_f) + __expf(snk - m_f);
    float inv = 1.0f / l_f;

    size_t base = (((size_t)(b * S_LEN + i_glob)) * NH + h) * HD;
#pragma unroll
    for (int d = 0; d < HD; d++) {
        float a = acc[d] * se;
        a += __shfl_xor_sync(0xffffffffu, a, 1);
        acc[d] = a * inv;
    }
    // both threads of the pair hold identical results; split the store
#pragma unroll
    for (int d = half * 32; d < half * 32 + 32; d += 4) {
        *(float4*)&ctx[base + d] =
            make_float4(acc[d], acc[d + 1], acc[d + 2], acc[d + 3]);
    }
}

// ---------------- launch -----------------------------------------------------
extern "C" void kernel_launch(void* const* d_in, const int* in_sizes, int n_in,
                              void* d_out, int out_size)
{
    const float* x     = (const float*)d_in[0];
    const float* Wq    = (const float*)d_in[1];
    const float* bq    = (const float*)d_in[2];
    const float* Wk    = (const float*)d_in[3];
    const float* bk    = (const float*)d_in[4];
    const float* Wv    = (const float*)d_in[5];
    const float* bv    = (const float*)d_in[6];
    const float* Wo    = (const float*)d_in[7];
    const float* bo    = (const float*)d_in[8];
    const float* sinks = (const float*)d_in[9];
    const int*   pos   = (const int*)d_in[10];
    float* out = (float*)d_out;

    float *gQ, *gK, *gV, *gctx;
    cudaGetSymbolAddress((void**)&gQ, g_Q);
    cudaGetSymbolAddress((void**)&gK, g_K);
    cudaGetSymbolAddress((void**)&gV, g_V);
    cudaGetSymbolAddress((void**)&gctx, g_ctx);

    // projections
    sgemm_nt<<<dim3(16, 32), 256>>>(x, Wq, bq, gQ, MSEQ, NH * HD, EMB);
    sgemm_nt<<<dim3(4, 32), 256>>>(x, Wk, bk, gK, MSEQ, NKV * HD, EMB);
    sgemm_nt<<<dim3(4, 32), 256>>>(x, Wv, bv, gV, MSEQ, NKV * HD, EMB);

    // RoPE on Q and K
    rope_kernel<<<(MSEQ * NH * 32 + 255) / 256, 256>>>(gQ, pos, MSEQ, NH);
    rope_kernel<<<(MSEQ * NKV * 32 + 255) / 256, 256>>>(gK, pos, MSEQ, NKV);

    // windowed attention with sink
    attn_kernel<<<dim3(S_LEN / 64, NH, BATCH), 128>>>(gQ, gK, gV, sinks, gctx);

    // output projection
    sgemm_nt<<<dim3(16, 32), 256>>>(gctx, Wo, bo, out, MSEQ, EMB, EMB);
}

// round 8
// speedup vs baseline: 1.8886x; 1.8879x over previous
#include <cuda_runtime.h>
#include <cuda_bf16.h>
#include <cstdint>

#define S_LEN 2048
#define BATCH 2
#define EMB 2048
#define NH 32
#define NKV 8
#define HD 64
#define WIN 128
#define MSEQ 4096   // B*S rows

// ---------------- scratch (static device globals; no allocation allowed) ----
__device__ __align__(256) float g_Q[MSEQ * NH * HD];     // 32 MB
__device__ __align__(256) float g_K[MSEQ * NKV * HD];    // 8 MB
__device__ __align__(256) float g_V[MSEQ * NKV * HD];    // 8 MB

// bf16 hi/lo planes
__device__ __align__(256) __nv_bfloat16 g_xh[MSEQ * EMB];
__device__ __align__(256) __nv_bfloat16 g_xl[MSEQ * EMB];
__device__ __align__(256) __nv_bfloat16 g_Wqh[2048 * 2048];
__device__ __align__(256) __nv_bfloat16 g_Wql[2048 * 2048];
__device__ __align__(256) __nv_bfloat16 g_Wkh[512 * 2048];
__device__ __align__(256) __nv_bfloat16 g_Wkl[512 * 2048];
__device__ __align__(256) __nv_bfloat16 g_Wvh[512 * 2048];
__device__ __align__(256) __nv_bfloat16 g_Wvl[512 * 2048];
__device__ __align__(256) __nv_bfloat16 g_Woh[2048 * 2048];
__device__ __align__(256) __nv_bfloat16 g_Wol[2048 * 2048];
__device__ __align__(256) __nv_bfloat16 g_ch[MSEQ * 2048];
__device__ __align__(256) __nv_bfloat16 g_cl[MSEQ * 2048];

// ---------------- helpers ---------------------------------------------------
__device__ __forceinline__ uint32_t smem_u32(const void* p) {
    uint32_t a;
    asm("{ .reg .u64 t; cvta.to.shared.u64 t, %1; cvt.u32.u64 %0, t; }"
        : "=r"(a) : "l"(p));
    return a;
}

#define CP16(dst, src) \
    asm volatile("cp.async.cg.shared.global [%0], [%1], 16;" \
                 :: "r"(dst), "l"(src) : "memory")
#define CP_COMMIT() asm volatile("cp.async.commit_group;" ::: "memory")
#define CP_WAIT0()  asm volatile("cp.async.wait_group 0;" ::: "memory")
#define CP_WAIT1()  asm volatile("cp.async.wait_group 1;" ::: "memory")

__device__ __forceinline__ void ldsm4(uint32_t* r, uint32_t addr) {
    asm volatile("ldmatrix.sync.aligned.m8n8.x4.shared.b16 {%0,%1,%2,%3}, [%4];"
                 : "=r"(r[0]), "=r"(r[1]), "=r"(r[2]), "=r"(r[3]) : "r"(addr));
}

__device__ __forceinline__ void mma16816(float* d, const uint32_t* a,
                                         uint32_t b0, uint32_t b1) {
    asm volatile(
        "mma.sync.aligned.m16n8k16.row.col.f32.bf16.bf16.f32 "
        "{%0,%1,%2,%3}, {%4,%5,%6,%7}, {%8,%9}, {%0,%1,%2,%3};"
        : "+f"(d[0]), "+f"(d[1]), "+f"(d[2]), "+f"(d[3])
        : "r"(a[0]), "r"(a[1]), "r"(a[2]), "r"(a[3]), "r"(b0), "r"(b1));
}

__device__ __forceinline__ uint32_t packb2(__nv_bfloat16 a, __nv_bfloat16 b) {
    __nv_bfloat162 t = __halves2bfloat162(a, b);
    return *reinterpret_cast<uint32_t*>(&t);
}

// ---------------- fp32 -> bf16 hi/lo split ----------------------------------
__global__ void cvt_split(const float* __restrict__ in,
                          __nv_bfloat16* __restrict__ hi,
                          __nv_bfloat16* __restrict__ lo, int n)
{
    int i = (blockIdx.x * blockDim.x + threadIdx.x) * 4;
    if (i >= n) return;
    float4 v = *(const float4*)(in + i);
    __nv_bfloat16 h0 = __float2bfloat16(v.x), h1 = __float2bfloat16(v.y);
    __nv_bfloat16 h2 = __float2bfloat16(v.z), h3 = __float2bfloat16(v.w);
    uint2 H = make_uint2(packb2(h0, h1), packb2(h2, h3));
    uint2 L = make_uint2(
        packb2(__float2bfloat16(v.x - __bfloat162float(h0)),
               __float2bfloat16(v.y - __bfloat162float(h1))),
        packb2(__float2bfloat16(v.z - __bfloat162float(h2)),
               __float2bfloat16(v.w - __bfloat162float(h3))));
    *(uint2*)(hi + i) = H;
    *(uint2*)(lo + i) = L;
}

// ============ tensor-core GEMM: C[M,N] = A[M,K]*B[N,K]^T + bias =============
// bf16 hi/lo planes, 3-pass split, fp32 accum.
// BM=BN=128, BK=64, 256 threads, warp tile 32x64 (8 warps: 4m x 2n).
// smem rows padded to 72 bf16 (144B) -> conflict-free ldmatrix.
#define GSTRIDE 144                     // bytes per smem row
#define PLANE_B (128 * GSTRIDE)         // 18432 B per plane
#define STAGE_B (4 * PLANE_B)           // Ah, Al, Bh, Bl
#define GEMM_SMEM (2 * STAGE_B)         // 147456 B

__global__ __launch_bounds__(256, 1)
void gemm_bf16(const __nv_bfloat16* __restrict__ Ah,
               const __nv_bfloat16* __restrict__ Al,
               const __nv_bfloat16* __restrict__ Bh,
               const __nv_bfloat16* __restrict__ Bl,
               const float* __restrict__ bias, float* __restrict__ C,
               int M, int N, int K)
{
    extern __shared__ char sm[];
    const uint32_t sb = smem_u32(sm);
    const int tid = threadIdx.x;
    const int wid = tid >> 5;
    const int lane = tid & 31;
    const int warp_m = wid & 3;          // 0..3 -> 32-row slice
    const int warp_n = wid >> 2;         // 0..1 -> 64-col slice
    const int m0 = blockIdx.y * 128;
    const int n0 = blockIdx.x * 128;

    float acc[2][8][4];
#pragma unroll
    for (int a = 0; a < 2; a++)
#pragma unroll
        for (int b = 0; b < 8; b++)
#pragma unroll
            for (int c = 0; c < 4; c++) acc[a][b][c] = 0.f;

    const __nv_bfloat16* srcs[4] = {Ah, Al, Bh, Bl};

    auto stage = [&](int buf, int k0) {
        uint32_t dbase = sb + buf * STAGE_B;
#pragma unroll
        for (int p = 0; p < 4; p++) {
            const __nv_bfloat16* s = srcs[p];
            int rbase = (p < 2) ? m0 : n0;
#pragma unroll
            for (int it = 0; it < 4; it++) {
                int l = tid + it * 256;        // 0..1023
                int row = l >> 3;              // 0..127
                int grp = l & 7;               // 16B group within 128B row
                CP16(dbase + p * PLANE_B + row * GSTRIDE + grp * 16,
                     s + (size_t)(rbase + row) * K + k0 + grp * 8);
            }
        }
    };

    // per-lane ldmatrix offset within a 16x16 tile
    const uint32_t loff =
        ((lane & 7) + ((lane >> 3) & 1) * 8) * GSTRIDE + (lane >> 4) * 16;

    auto compute = [&](int buf) {
        uint32_t base = sb + buf * STAGE_B;
        uint32_t aAh = base + 0 * PLANE_B + (warp_m * 32) * GSTRIDE + loff;
        uint32_t aAl = base + 1 * PLANE_B + (warp_m * 32) * GSTRIDE + loff;
        uint32_t aBh = base + 2 * PLANE_B + (warp_n * 64) * GSTRIDE + loff;
        uint32_t aBl = base + 3 * PLANE_B + (warp_n * 64) * GSTRIDE + loff;
#pragma unroll
        for (int ks = 0; ks < 4; ks++) {
            uint32_t ck = ks * 32;             // 16 bf16 = 32 bytes per k-step
            uint32_t ah[2][4], al[2][4], bb[4][4];
            ldsm4(ah[0], aAh + ck);
            ldsm4(ah[1], aAh + 16 * GSTRIDE + ck);
            ldsm4(al[0], aAl + ck);
            ldsm4(al[1], aAl + 16 * GSTRIDE + ck);
#pragma unroll
            for (int g = 0; g < 4; g++)
                ldsm4(bb[g], aBh + g * 16 * GSTRIDE + ck);
#pragma unroll
            for (int mt = 0; mt < 2; mt++)
#pragma unroll
                for (int nt = 0; nt < 8; nt++) {
                    uint32_t b0 = bb[nt >> 1][nt & 1];
                    uint32_t b1 = bb[nt >> 1][2 + (nt & 1)];
                    mma16816(acc[mt][nt], ah[mt], b0, b1);   // Ah*Bh
                    mma16816(acc[mt][nt], al[mt], b0, b1);   // Al*Bh
                }
#pragma unroll
            for (int g = 0; g < 4; g++)
                ldsm4(bb[g], aBl + g * 16 * GSTRIDE + ck);
#pragma unroll
            for (int mt = 0; mt < 2; mt++)
#pragma unroll
                for (int nt = 0; nt < 8; nt++) {
                    uint32_t b0 = bb[nt >> 1][nt & 1];
                    uint32_t b1 = bb[nt >> 1][2 + (nt & 1)];
                    mma16816(acc[mt][nt], ah[mt], b0, b1);   // Ah*Bl
                }
        }
    };

    stage(0, 0);
    CP_COMMIT();
    const int nch = K >> 6;
    int buf = 0;
    for (int ci = 0; ci < nch; ci++) {
        if (ci + 1 < nch) {
            stage(buf ^ 1, (ci + 1) << 6);
            CP_COMMIT();
            CP_WAIT1();
        } else {
            CP_WAIT0();
        }
        __syncthreads();
        compute(buf);
        __syncthreads();
        buf ^= 1;
    }

    // ---- epilogue: fragment -> gmem (8B stores, sector-aligned) ----
#pragma unroll
    for (int mt = 0; mt < 2; mt++) {
        int row = m0 + warp_m * 32 + mt * 16 + (lane >> 2);
#pragma unroll
        for (int nt = 0; nt < 8; nt++) {
            int col = n0 + warp_n * 64 + nt * 8 + (lane & 3) * 2;
            float2 bv = *(const float2*)&bias[col];
            float2 v0 = make_float2(acc[mt][nt][0] + bv.x, acc[mt][nt][1] + bv.y);
            float2 v1 = make_float2(acc[mt][nt][2] + bv.x, acc[mt][nt][3] + bv.y);
            *(float2*)&C[(size_t)row * N + col] = v0;
            *(float2*)&C[(size_t)(row + 8) * N + col] = v1;
        }
    }
}

// ---------------- YaRN RoPE (in-place), one thread per (bs, head, pair) -----
__global__ void rope_kernel(float* __restrict__ X, const int* __restrict__ pos_ids,
                            int BS, int H)
{
    int idx = blockIdx.x * blockDim.x + threadIdx.x;
    int total = BS * H * (HD / 2);
    if (idx >= total) return;
    int i = idx & 31;
    int h = (idx >> 5) % H;
    int bs = idx / (32 * H);

    float pos = (float)pos_ids[bs];
    float freq = expf(-((float)(2 * i) * (1.0f / 64.0f)) * 9.210340371976184f);
    float wl = 6.283185307179586f / freq;
    float t = (wl - 32.0f) * (1.0f / 992.0f);
    t = fminf(fmaxf(t, 0.0f), 1.0f);
    float eff = freq * (1.0f - t) + freq * 0.25f * t;
    float ang = pos * eff * 1.1386294361119891f;
    float s, c;
    sincosf(ang, &s, &c);

    float* p = X + ((size_t)bs * H + h) * HD;
    float x1 = p[i];
    float x2 = p[i + 32];
    p[i] = x1 * c - x2 * s;
    p[i + 32] = x2 * c + x1 * s;
}

// ---------------- sliding-window attention with sink ------------------------
// writes ctx directly as bf16 hi/lo planes (input to O-proj tensor GEMM)
__global__ __launch_bounds__(128) void attn_kernel(
    const float* __restrict__ Q, const float* __restrict__ K,
    const float* __restrict__ V, const float* __restrict__ sinks,
    __nv_bfloat16* __restrict__ ctxh, __nv_bfloat16* __restrict__ ctxl)
{
    __shared__ float Qs[64][HD];
    __shared__ float Ks[64][HD];
    __shared__ float Vs[64][HD];

    const int b = blockIdx.z;
    const int h = blockIdx.y;
    const int q0 = blockIdx.x * 64;
    const int kvh = h >> 2;            // GS = 4
    const int tid = threadIdx.x;
    const int r = tid >> 1;
    const int half = tid & 1;
    const int i_glob = q0 + r;

#pragma unroll
    for (int it = 0; it < 8; it++) {
        int l = tid + it * 128;
        int row = l >> 4;
        int dd = (l & 15) << 2;
        *(float4*)&Qs[row][dd] =
            *(const float4*)&Q[(((size_t)(b * S_LEN + q0 + row)) * NH + h) * HD + dd];
    }

    float m = -1e30f, lsum = 0.f;
    float acc[HD];
#pragma unroll
    for (int d = 0; d < HD; d++) acc[d] = 0.f;

    const int kt_begin = (q0 >= WIN) ? (q0 - WIN) : 0;
    for (int kts = kt_begin; kts <= q0; kts += 64) {
        __syncthreads();
#pragma unroll
        for (int it = 0; it < 8; it++) {
            int l = tid + it * 128;
            int row = l >> 4;
            int dd = (l & 15) << 2;
            size_t g = (((size_t)(b * S_LEN + kts + row)) * NKV + kvh) * HD + dd;
            *(float4*)&Ks[row][dd] = *(const float4*)&K[g];
            *(float4*)&Vs[row][dd] = *(const float4*)&V[g];
        }
        __syncthreads();

        float sc[32];
#pragma unroll
        for (int c = 0; c < 32; c++) sc[c] = 0.f;
#pragma unroll
        for (int dc = 0; dc < HD; dc += 8) {
            float4 qa = *(float4*)&Qs[r][dc];
            float4 qb = *(float4*)&Qs[r][dc + 4];
#pragma unroll
            for (int c = 0; c < 32; c++) {
                const float* kp = &Ks[half * 32 + c][dc];
                float4 ka = *(const float4*)kp;
                float4 kb = *(const float4*)(kp + 4);
                sc[c] += qa.x * ka.x + qa.y * ka.y + qa.z * ka.z + qa.w * ka.w
                       + qb.x * kb.x + qb.y * kb.y + qb.z * kb.z + qb.w * kb.w;
            }
        }

        float tmax = -1e30f;
#pragma unroll
        for (int c = 0; c < 32; c++) {
            int j = kts + half * 32 + c;
            bool ok = (j <= i_glob) && (j > i_glob - WIN);
            sc[c] = ok ? sc[c] * 0.125f : -1e30f;
            tmax = fmaxf(tmax, sc[c]);
        }
        float m_new = fmaxf(m, tmax);
        if (m_new > -1e29f) {
            float corr = __expf(m - m_new);
            lsum *= corr;
#pragma unroll
            for (int d = 0; d < HD; d++) acc[d] *= corr;
#pragma unroll
            for (int c = 0; c < 32; c++) {
                float p = __expf(sc[c] - m_new);
                lsum += p;
                const float* vp = &Vs[half * 32 + c][0];
#pragma unroll
                for (int d = 0; d < HD; d += 4) {
                    float4 v = *(const float4*)(vp + d);
                    acc[d + 0] += p * v.x;
                    acc[d + 1] += p * v.y;
                    acc[d + 2] += p * v.z;
                    acc[d + 3] += p * v.w;
                }
            }
            m = m_new;
        }
    }

    float m_o = __shfl_xor_sync(0xffffffffu, m, 1);
    float l_o = __shfl_xor_sync(0xffffffffu, lsum, 1);
    float snk = sinks[h];
    float m_f = fmaxf(fmaxf(m, m_o), snk);
    float se = __expf(m - m_f);
    float l_f = lsum * se + l_o * __expf(m_o - m_f) + __expf(snk - m_f);
    float inv = 1.0f / l_f;

    size_t base = ((size_t)(b * S_LEN + i_glob)) * (NH * HD) + h * HD;
#pragma unroll
    for (int d = 0; d < HD; d++) {
        float a = acc[d] * se;
        a += __shfl_xor_sync(0xffffffffu, a, 1);
        acc[d] = a * inv;
    }
    // write hi/lo bf16 planes (both pair threads hold identical values; split cols)
#pragma unroll
    for (int d = half * 32; d < half * 32 + 32; d += 2) {
        float a0 = acc[d], a1 = acc[d + 1];
        __nv_bfloat16 h0 = __float2bfloat16(a0), h1 = __float2bfloat16(a1);
        *(uint32_t*)(ctxh + base + d) = packb2(h0, h1);
        *(uint32_t*)(ctxl + base + d) =
            packb2(__float2bfloat16(a0 - __bfloat162float(h0)),
                   __float2bfloat16(a1 - __bfloat162float(h1)));
    }
}

// ---------------- launch -----------------------------------------------------
extern "C" void kernel_launch(void* const* d_in, const int* in_sizes, int n_in,
                              void* d_out, int out_size)
{
    const float* x     = (const float*)d_in[0];
    const float* Wq    = (const float*)d_in[1];
    const float* bq    = (const float*)d_in[2];
    const float* Wk    = (const float*)d_in[3];
    const float* bk    = (const float*)d_in[4];
    const float* Wv    = (const float*)d_in[5];
    const float* bv    = (const float*)d_in[6];
    const float* Wo    = (const float*)d_in[7];
    const float* bo    = (const float*)d_in[8];
    const float* sinks = (const float*)d_in[9];
    const int*   pos   = (const int*)d_in[10];
    float* out = (float*)d_out;

    float *gQ, *gK, *gV;
    __nv_bfloat16 *xh, *xl, *qh, *ql, *kh, *kl, *vh, *vl, *oh, *ol, *ch, *cl;
    cudaGetSymbolAddress((void**)&gQ, g_Q);
    cudaGetSymbolAddress((void**)&gK, g_K);
    cudaGetSymbolAddress((void**)&gV, g_V);
    cudaGetSymbolAddress((void**)&xh, g_xh);
    cudaGetSymbolAddress((void**)&xl, g_xl);
    cudaGetSymbolAddress((void**)&qh, g_Wqh);
    cudaGetSymbolAddress((void**)&ql, g_Wql);
    cudaGetSymbolAddress((void**)&kh, g_Wkh);
    cudaGetSymbolAddress((void**)&kl, g_Wkl);
    cudaGetSymbolAddress((void**)&vh, g_Wvh);
    cudaGetSymbolAddress((void**)&vl, g_Wvl);
    cudaGetSymbolAddress((void**)&oh, g_Woh);
    cudaGetSymbolAddress((void**)&ol, g_Wol);
    cudaGetSymbolAddress((void**)&ch, g_ch);
    cudaGetSymbolAddress((void**)&cl, g_cl);

    cudaFuncSetAttribute(gemm_bf16, cudaFuncAttributeMaxDynamicSharedMemorySize,
                         GEMM_SMEM);

    // hi/lo splits
    cvt_split<<<(MSEQ * EMB / 4 + 255) / 256, 256>>>(x, xh, xl, MSEQ * EMB);
    cvt_split<<<(2048 * 2048 / 4 + 255) / 256, 256>>>(Wq, qh, ql, 2048 * 2048);
    cvt_split<<<(512 * 2048 / 4 + 255) / 256, 256>>>(Wk, kh, kl, 512 * 2048);
    cvt_split<<<(512 * 2048 / 4 + 255) / 256, 256>>>(Wv, vh, vl, 512 * 2048);
    cvt_split<<<(2048 * 2048 / 4 + 255) / 256, 256>>>(Wo, oh, ol, 2048 * 2048);

    // projections (tensor cores, 3-pass bf16 split)
    gemm_bf16<<<dim3(16, 32), 256, GEMM_SMEM>>>(xh, xl, qh, ql, bq, gQ,
                                                MSEQ, NH * HD, EMB);
    gemm_bf16<<<dim3(4, 32), 256, GEMM_SMEM>>>(xh, xl, kh, kl, bk, gK,
                                               MSEQ, NKV * HD, EMB);
    gemm_bf16<<<dim3(4, 32), 256, GEMM_SMEM>>>(xh, xl, vh, vl, bv, gV,
                                               MSEQ, NKV * HD, EMB);

    // RoPE on Q and K
    rope_kernel<<<(MSEQ * NH * 32 + 255) / 256, 256>>>(gQ, pos, MSEQ, NH);
    rope_kernel<<<(MSEQ * NKV * 32 + 255) / 256, 256>>>(gK, pos, MSEQ, NKV);

    // windowed attention with sink -> ctx hi/lo planes
    attn_kernel<<<dim3(S_LEN / 64, NH, BATCH), 128>>>(gQ, gK, gV, sinks, ch, cl);

    // output projection
    gemm_bf16<<<dim3(16, 32), 256, GEMM_SMEM>>>(ch, cl, oh, ol, bo, out,
                                                MSEQ, EMB, EMB);
}

// round 9
// speedup vs baseline: 3.4713x; 1.8380x over previous
#include <cuda_runtime.h>
#include <cuda_fp16.h>
#include <cstdint>

#define S_LEN 2048
#define BATCH 2
#define EMB 2048
#define NH 32
#define NKV 8
#define HD 64
#define WIN 128
#define MSEQ 4096   // B*S rows

#define NXE (MSEQ * EMB)       // 8388608
#define NQE (2048 * 2048)      // 4194304
#define NKE (512 * 2048)       // 1048576

// ---------------- scratch (static device globals; no allocation allowed) ----
__device__ __align__(256) float g_Q[MSEQ * NH * HD];     // 32 MB
__device__ __align__(256) float g_K[MSEQ * NKV * HD];    // 8 MB
__device__ __align__(256) float g_V[MSEQ * NKV * HD];    // 8 MB

__device__ __align__(256) __half g_xh[NXE];
__device__ __align__(256) __half g_Wqh[NQE];
__device__ __align__(256) __half g_Wkh[NKE];
__device__ __align__(256) __half g_Wvh[NKE];
__device__ __align__(256) __half g_Woh[NQE];
__device__ __align__(256) __half g_ch[MSEQ * 2048];

// ---------------- helpers ---------------------------------------------------
__device__ __forceinline__ uint32_t smem_u32(const void* p) {
    uint32_t a;
    asm("{ .reg .u64 t; cvta.to.shared.u64 t, %1; cvt.u32.u64 %0, t; }"
        : "=r"(a) : "l"(p));
    return a;
}

#define CP16(dst, src) \
    asm volatile("cp.async.cg.shared.global [%0], [%1], 16;" \
                 :: "r"(dst), "l"(src) : "memory")
#define CP_COMMIT() asm volatile("cp.async.commit_group;" ::: "memory")
#define CP_WAIT0()  asm volatile("cp.async.wait_group 0;" ::: "memory")
#define CP_WAIT1()  asm volatile("cp.async.wait_group 1;" ::: "memory")

__device__ __forceinline__ void ldsm4(uint32_t* r, uint32_t addr) {
    asm volatile("ldmatrix.sync.aligned.m8n8.x4.shared.b16 {%0,%1,%2,%3}, [%4];"
                 : "=r"(r[0]), "=r"(r[1]), "=r"(r[2]), "=r"(r[3]) : "r"(addr));
}

__device__ __forceinline__ void mma16816(float* d, const uint32_t* a,
                                         uint32_t b0, uint32_t b1) {
    asm volatile(
        "mma.sync.aligned.m16n8k16.row.col.f32.f16.f16.f32 "
        "{%0,%1,%2,%3}, {%4,%5,%6,%7}, {%8,%9}, {%0,%1,%2,%3};"
        : "+f"(d[0]), "+f"(d[1]), "+f"(d[2]), "+f"(d[3])
        : "r"(a[0]), "r"(a[1]), "r"(a[2]), "r"(a[3]), "r"(b0), "r"(b1));
}

// ---------------- fp32 -> fp16 convert for all 5 tensors, one launch --------
__global__ void cvt5(const float* __restrict__ x,  const float* __restrict__ wq,
                     const float* __restrict__ wk, const float* __restrict__ wv,
                     const float* __restrict__ wo,
                     __half* __restrict__ xh, __half* __restrict__ wqh,
                     __half* __restrict__ wkh, __half* __restrict__ wvh,
                     __half* __restrict__ woh)
{
    long i = (long)(blockIdx.x * blockDim.x + threadIdx.x) * 4;
    const float* s; __half* d; long off;
    if (i < NXE)                              { s = x;  d = xh;  off = i; }
    else if ((off = i - NXE) < NQE)           { s = wq; d = wqh; }
    else if ((off = i - NXE - NQE) < NKE)     { s = wk; d = wkh; }
    else if ((off = i - NXE - NQE - NKE) < NKE) { s = wv; d = wvh; }
    else {
        off = i - NXE - NQE - 2L * NKE;
        if (off >= NQE) return;
        s = wo; d = woh;
    }
    float4 v = *(const float4*)(s + off);
    __half2 a = __floats2half2_rn(v.x, v.y);
    __half2 b = __floats2half2_rn(v.z, v.w);
    uint2 u = make_uint2(*(uint32_t*)&a, *(uint32_t*)&b);
    *(uint2*)(d + off) = u;
}

// ============ tensor-core GEMM core: acc += A[128,K] * B[128,K]^T ===========
// fp16 single-pass, fp32 accum. BM=BN=128, BK=64, 256 threads,
// warp tile 32x64 (8 warps: 4m x 2n). smem rows padded to 144B.
#define GSTRIDE 144
#define PLANE_B (128 * GSTRIDE)     // 18432 B
#define STAGE_B (2 * PLANE_B)       // A + B
#define GEMM_SMEM (2 * STAGE_B)     // 73728 B

__device__ __forceinline__ void gemm_core(const __half* __restrict__ A,
                                          const __half* __restrict__ B,
                                          int K, int m0, int n0, char* sm,
                                          float (&acc)[2][8][4])
{
    const uint32_t sb = smem_u32(sm);
    const int tid = threadIdx.x;
    const int wid = tid >> 5;
    const int lane = tid & 31;
    const int warp_m = wid & 3;
    const int warp_n = wid >> 2;

#pragma unroll
    for (int a = 0; a < 2; a++)
#pragma unroll
        for (int b = 0; b < 8; b++)
#pragma unroll
            for (int c = 0; c < 4; c++) acc[a][b][c] = 0.f;

    auto stage = [&](int buf, int k0) {
        uint32_t dbase = sb + buf * STAGE_B;
#pragma unroll
        for (int it = 0; it < 4; it++) {
            int l = tid + it * 256;        // 0..1023
            int row = l >> 3;              // 0..127
            int grp = l & 7;
            CP16(dbase + row * GSTRIDE + grp * 16,
                 A + (size_t)(m0 + row) * K + k0 + grp * 8);
            CP16(dbase + PLANE_B + row * GSTRIDE + grp * 16,
                 B + (size_t)(n0 + row) * K + k0 + grp * 8);
        }
    };

    const uint32_t loff =
        ((lane & 7) + ((lane >> 3) & 1) * 8) * GSTRIDE + (lane >> 4) * 16;

    auto compute = [&](int buf) {
        uint32_t base = sb + buf * STAGE_B;
        uint32_t aA = base + (warp_m * 32) * GSTRIDE + loff;
        uint32_t aB = base + PLANE_B + (warp_n * 64) * GSTRIDE + loff;
#pragma unroll
        for (int ks = 0; ks < 4; ks++) {
            uint32_t ck = ks * 32;
            uint32_t ah[2][4], bb[4][4];
            ldsm4(ah[0], aA + ck);
            ldsm4(ah[1], aA + 16 * GSTRIDE + ck);
#pragma unroll
            for (int g = 0; g < 4; g++)
                ldsm4(bb[g], aB + g * 16 * GSTRIDE + ck);
#pragma unroll
            for (int mt = 0; mt < 2; mt++)
#pragma unroll
                for (int nt = 0; nt < 8; nt++)
                    mma16816(acc[mt][nt], ah[mt],
                             bb[nt >> 1][nt & 1], bb[nt >> 1][2 + (nt & 1)]);
        }
    };

    stage(0, 0);
    CP_COMMIT();
    const int nch = K >> 6;
    int buf = 0;
    for (int ci = 0; ci < nch; ci++) {
        if (ci + 1 < nch) {
            stage(buf ^ 1, (ci + 1) << 6);
            CP_COMMIT();
            CP_WAIT1();
        } else {
            CP_WAIT0();
        }
        __syncthreads();
        compute(buf);
        __syncthreads();
        buf ^= 1;
    }
}

// plain epilogue: + bias, store fp32
__device__ __forceinline__ void epi_plain(float (&acc)[2][8][4],
                                          const float* __restrict__ bias,
                                          float* __restrict__ C, int N,
                                          int m0, int n0)
{
    const int tid = threadIdx.x;
    const int wid = tid >> 5;
    const int lane = tid & 31;
    const int warp_m = wid & 3;
    const int warp_n = wid >> 2;
#pragma unroll
    for (int mt = 0; mt < 2; mt++) {
        int row = m0 + warp_m * 32 + mt * 16 + (lane >> 2);
#pragma unroll
        for (int nt = 0; nt < 8; nt++) {
            int col = n0 + warp_n * 64 + nt * 8 + (lane & 3) * 2;
            float2 bv = *(const float2*)&bias[col];
            *(float2*)&C[(size_t)row * N + col] =
                make_float2(acc[mt][nt][0] + bv.x, acc[mt][nt][1] + bv.y);
            *(float2*)&C[(size_t)(row + 8) * N + col] =
                make_float2(acc[mt][nt][2] + bv.x, acc[mt][nt][3] + bv.y);
        }
    }
}

// rope epilogue: + bias, apply YaRN rope (pairs nt <-> nt+4), store fp32
__device__ __forceinline__ void epi_rope(float (&acc)[2][8][4],
                                         const float* __restrict__ bias,
                                         float* __restrict__ C, int N,
                                         int m0, int n0,
                                         const int* __restrict__ pos)
{
    const int tid = threadIdx.x;
    const int wid = tid >> 5;
    const int lane = tid & 31;
    const int warp_m = wid & 3;
    const int warp_n = wid >> 2;

    int rbase = m0 + warp_m * 32 + (lane >> 2);
    float posr[4];
    posr[0] = (float)pos[rbase];
    posr[1] = (float)pos[rbase + 8];
    posr[2] = (float)pos[rbase + 16];
    posr[3] = (float)pos[rbase + 24];

    const float conc = 1.1386294361119891f;
#pragma unroll
    for (int nt = 0; nt < 4; nt++) {
        int i0 = nt * 8 + (lane & 3) * 2;
        // freq = 10000^(-i/32); eff = freq*(1 - 0.75*t), t = clamp((wl-32)/992)
        float fr0 = expf(-(float)i0 * 0.2878231366242557f);
        float fr1 = expf(-(float)(i0 + 1) * 0.2878231366242557f);
        float wl0 = 6.283185307179586f / fr0;
        float wl1 = 6.283185307179586f / fr1;
        float t0 = fminf(fmaxf((wl0 - 32.0f) * (1.0f / 992.0f), 0.f), 1.f);
        float t1 = fminf(fmaxf((wl1 - 32.0f) * (1.0f / 992.0f), 0.f), 1.f);
        float e0 = fr0 * (1.0f - 0.75f * t0) * conc;
        float e1 = fr1 * (1.0f - 0.75f * t1) * conc;

        int c0 = n0 + warp_n * 64 + i0;
        float2 b1 = *(const float2*)&bias[c0];
        float2 b2 = *(const float2*)&bias[c0 + 32];
#pragma unroll
        for (int mt = 0; mt < 2; mt++)
#pragma unroll
            for (int sub = 0; sub < 2; sub++) {
                int row = m0 + warp_m * 32 + mt * 16 + (lane >> 2) + sub * 8;
                float p = posr[mt * 2 + sub];
                float s0, cs0, s1, cs1;
                sincosf(p * e0, &s0, &cs0);
                sincosf(p * e1, &s1, &cs1);
                float x1a = acc[mt][nt][sub * 2 + 0] + b1.x;
                float x1b = acc[mt][nt][sub * 2 + 1] + b1.y;
                float x2a = acc[mt][nt + 4][sub * 2 + 0] + b2.x;
                float x2b = acc[mt][nt + 4][sub * 2 + 1] + b2.y;
                *(float2*)&C[(size_t)row * N + c0] =
                    make_float2(x1a * cs0 - x2a * s0, x1b * cs1 - x2b * s1);
                *(float2*)&C[(size_t)row * N + c0 + 32] =
                    make_float2(x2a * cs0 + x1a * s0, x2b * cs1 + x1b * s1);
            }
    }
}

// merged Q/K/V projection (+ fused rope on Q,K). grid (24, 32)
__global__ __launch_bounds__(256, 2)
void gemm_qkv(const __half* __restrict__ A,
              const __half* __restrict__ Bq, const __half* __restrict__ Bk,
              const __half* __restrict__ Bv,
              const float* __restrict__ bq, const float* __restrict__ bk,
              const float* __restrict__ bv,
              float* __restrict__ Cq, float* __restrict__ Ck,
              float* __restrict__ Cv, const int* __restrict__ pos)
{
    extern __shared__ char sm[];
    const int bx = blockIdx.x;
    const int m0 = blockIdx.y * 128;
    const __half* B; const float* bias; float* C; int N, n0; bool rope = true;
    if (bx < 16)      { B = Bq; bias = bq; C = Cq; N = 2048; n0 = bx << 7; }
    else if (bx < 20) { B = Bk; bias = bk; C = Ck; N = 512; n0 = (bx - 16) << 7; }
    else              { B = Bv; bias = bv; C = Cv; N = 512; n0 = (bx - 20) << 7; rope = false; }

    float acc[2][8][4];
    gemm_core(A, B, EMB, m0, n0, sm, acc);
    if (rope) epi_rope(acc, bias, C, N, m0, n0, pos);
    else      epi_plain(acc, bias, C, N, m0, n0);
}

// output projection. grid (16, 32)
__global__ __launch_bounds__(256, 2)
void gemm_o(const __half* __restrict__ A, const __half* __restrict__ B,
            const float* __restrict__ bias, float* __restrict__ C)
{
    extern __shared__ char sm[];
    const int m0 = blockIdx.y * 128;
    const int n0 = blockIdx.x * 128;
    float acc[2][8][4];
    gemm_core(A, B, EMB, m0, n0, sm, acc);
    epi_plain(acc, bias, C, EMB, m0, n0);
}

// ---------------- sliding-window attention with sink ------------------------
// writes ctx directly as fp16 (input to O-proj tensor GEMM)
__global__ __launch_bounds__(128) void attn_kernel(
    const float* __restrict__ Q, const float* __restrict__ K,
    const float* __restrict__ V, const float* __restrict__ sinks,
    __half* __restrict__ ctxh)
{
    __shared__ float Qs[64][HD];
    __shared__ float Ks[64][HD];
    __shared__ float Vs[64][HD];

    const int b = blockIdx.z;
    const int h = blockIdx.y;
    const int q0 = blockIdx.x * 64;
    const int kvh = h >> 2;            // GS = 4
    const int tid = threadIdx.x;
    const int r = tid >> 1;
    const int half = tid & 1;
    const int i_glob = q0 + r;

#pragma unroll
    for (int it = 0; it < 8; it++) {
        int l = tid + it * 128;
        int row = l >> 4;
        int dd = (l & 15) << 2;
        *(float4*)&Qs[row][dd] =
            *(const float4*)&Q[(((size_t)(b * S_LEN + q0 + row)) * NH + h) * HD + dd];
    }

    float m = -1e30f, lsum = 0.f;
    float acc[HD];
#pragma unroll
    for (int d = 0; d < HD; d++) acc[d] = 0.f;

    const int kt_begin = (q0 >= WIN) ? (q0 - WIN) : 0;
    for (int kts = kt_begin; kts <= q0; kts += 64) {
        __syncthreads();
#pragma unroll
        for (int it = 0; it < 8; it++) {
            int l = tid + it * 128;
            int row = l >> 4;
            int dd = (l & 15) << 2;
            size_t g = (((size_t)(b * S_LEN + kts + row)) * NKV + kvh) * HD + dd;
            *(float4*)&Ks[row][dd] = *(const float4*)&K[g];
            *(float4*)&Vs[row][dd] = *(const float4*)&V[g];
        }
        __syncthreads();

        float sc[32];
#pragma unroll
        for (int c = 0; c < 32; c++) sc[c] = 0.f;
#pragma unroll
        for (int dc = 0; dc < HD; dc += 8) {
            float4 qa = *(float4*)&Qs[r][dc];
            float4 qb = *(float4*)&Qs[r][dc + 4];
#pragma unroll
            for (int c = 0; c < 32; c++) {
                const float* kp = &Ks[half * 32 + c][dc];
                float4 ka = *(const float4*)kp;
                float4 kb = *(const float4*)(kp + 4);
                sc[c] += qa.x * ka.x + qa.y * ka.y + qa.z * ka.z + qa.w * ka.w
                       + qb.x * kb.x + qb.y * kb.y + qb.z * kb.z + qb.w * kb.w;
            }
        }

        float tmax = -1e30f;
#pragma unroll
        for (int c = 0; c < 32; c++) {
            int j = kts + half * 32 + c;
            bool ok = (j <= i_glob) && (j > i_glob - WIN);
            sc[c] = ok ? sc[c] * 0.125f : -1e30f;
            tmax = fmaxf(tmax, sc[c]);
        }
        float m_new = fmaxf(m, tmax);
        if (m_new > -1e29f) {
            float corr = __expf(m - m_new);
            lsum *= corr;
#pragma unroll
            for (int d = 0; d < HD; d++) acc[d] *= corr;
#pragma unroll
            for (int c = 0; c < 32; c++) {
                float p = __expf(sc[c] - m_new);
                lsum += p;
                const float* vp = &Vs[half * 32 + c][0];
#pragma unroll
                for (int d = 0; d < HD; d += 4) {
                    float4 v = *(const float4*)(vp + d);
                    acc[d + 0] += p * v.x;
                    acc[d + 1] += p * v.y;
                    acc[d + 2] += p * v.z;
                    acc[d + 3] += p * v.w;
                }
            }
            m = m_new;
        }
    }

    float m_o = __shfl_xor_sync(0xffffffffu, m, 1);
    float l_o = __shfl_xor_sync(0xffffffffu, lsum, 1);
    float snk = sinks[h];
    float m_f = fmaxf(fmaxf(m, m_o), snk);
    float se = __expf(m - m_f);
    float l_f = lsum * se + l_o * __expf(m_o - m_f) + __expf(snk - m_f);
    float inv = 1.0f / l_f;

    size_t base = ((size_t)(b * S_LEN + i_glob)) * (NH * HD) + h * HD;
#pragma unroll
    for (int d = 0; d < HD; d++) {
        float a = acc[d] * se;
        a += __shfl_xor_sync(0xffffffffu, a, 1);
        acc[d] = a * inv;
    }
#pragma unroll
    for (int d = half * 32; d < half * 32 + 32; d += 2) {
        __half2 hv = __floats2half2_rn(acc[d], acc[d + 1]);
        *(uint32_t*)(ctxh + base + d) = *(uint32_t*)&hv;
    }
}

// ---------------- launch -----------------------------------------------------
extern "C" void kernel_launch(void* const* d_in, const int* in_sizes, int n_in,
                              void* d_out, int out_size)
{
    const float* x     = (const float*)d_in[0];
    const float* Wq    = (const float*)d_in[1];
    const float* bq    = (const float*)d_in[2];
    const float* Wk    = (const float*)d_in[3];
    const float* bk    = (const float*)d_in[4];
    const float* Wv    = (const float*)d_in[5];
    const float* bv    = (const float*)d_in[6];
    const float* Wo    = (const float*)d_in[7];
    const float* bo    = (const float*)d_in[8];
    const float* sinks = (const float*)d_in[9];
    const int*   pos   = (const int*)d_in[10];
    float* out = (float*)d_out;

    float *gQ, *gK, *gV;
    __half *xh, *qh, *kh, *vh, *oh, *ch;
    cudaGetSymbolAddress((void**)&gQ, g_Q);
    cudaGetSymbolAddress((void**)&gK, g_K);
    cudaGetSymbolAddress((void**)&gV, g_V);
    cudaGetSymbolAddress((void**)&xh, g_xh);
    cudaGetSymbolAddress((void**)&qh, g_Wqh);
    cudaGetSymbolAddress((void**)&kh, g_Wkh);
    cudaGetSymbolAddress((void**)&vh, g_Wvh);
    cudaGetSymbolAddress((void**)&oh, g_Woh);
    cudaGetSymbolAddress((void**)&ch, g_ch);

    cudaFuncSetAttribute(gemm_qkv, cudaFuncAttributeMaxDynamicSharedMemorySize,
                         GEMM_SMEM);
    cudaFuncSetAttribute(gemm_o, cudaFuncAttributeMaxDynamicSharedMemorySize,
                         GEMM_SMEM);

    // fp16 conversion of x and all weights, one launch
    int total4 = (NXE + 2 * NQE + 2 * NKE) / 4;
    cvt5<<<(total4 + 255) / 256, 256>>>(x, Wq, Wk, Wv, Wo, xh, qh, kh, vh, oh);

    // Q/K/V projections + fused YaRN rope (Q,K)
    gemm_qkv<<<dim3(24, 32), 256, GEMM_SMEM>>>(xh, qh, kh, vh, bq, bk, bv,
                                               gQ, gK, gV, pos);

    // windowed attention with sink -> ctx fp16
    attn_kernel<<<dim3(S_LEN / 64, NH, BATCH), 128>>>(gQ, gK, gV, sinks, ch);

    // output projection
    gemm_o<<<dim3(16, 32), 256, GEMM_SMEM>>>(ch, oh, bo, out);
}

// round 10
// speedup vs baseline: 7.0301x; 2.0252x over previous
#include <cuda_runtime.h>
#include <cuda_fp16.h>
#include <cstdint>

#define S_LEN 2048
#define BATCH 2
#define EMB 2048
#define NH 32
#define NKV 8
#define HD 64
#define WIN 128
#define MSEQ 4096   // B*S rows

#define NXE (MSEQ * EMB)       // 8388608
#define NQE (2048 * 2048)      // 4194304
#define NKE (512 * 2048)       // 1048576

// ---------------- scratch (static device globals; no allocation allowed) ----
__device__ __align__(256) __half g_Qa[MSEQ * NH * HD];    // fp16 Q (post-rope)
__device__ __align__(256) __half g_Ka[MSEQ * NKV * HD];   // fp16 K (post-rope)
__device__ __align__(256) __half g_Va[MSEQ * NKV * HD];   // fp16 V

__device__ __align__(256) __half g_xh[NXE];
__device__ __align__(256) __half g_Wqh[NQE];
__device__ __align__(256) __half g_Wkh[NKE];
__device__ __align__(256) __half g_Wvh[NKE];
__device__ __align__(256) __half g_Woh[NQE];
__device__ __align__(256) __half g_ch[MSEQ * 2048];

// ---------------- helpers ---------------------------------------------------
__device__ __forceinline__ uint32_t smem_u32(const void* p) {
    uint32_t a;
    asm("{ .reg .u64 t; cvta.to.shared.u64 t, %1; cvt.u32.u64 %0, t; }"
        : "=r"(a) : "l"(p));
    return a;
}

#define CP16(dst, src) \
    asm volatile("cp.async.cg.shared.global [%0], [%1], 16;" \
                 :: "r"(dst), "l"(src) : "memory")
#define CP_COMMIT() asm volatile("cp.async.commit_group;" ::: "memory")
#define CP_WAIT0()  asm volatile("cp.async.wait_group 0;" ::: "memory")
#define CP_WAIT1()  asm volatile("cp.async.wait_group 1;" ::: "memory")

__device__ __forceinline__ void ldsm4(uint32_t* r, uint32_t addr) {
    asm volatile("ldmatrix.sync.aligned.m8n8.x4.shared.b16 {%0,%1,%2,%3}, [%4];"
                 : "=r"(r[0]), "=r"(r[1]), "=r"(r[2]), "=r"(r[3]) : "r"(addr));
}
__device__ __forceinline__ void ldsm4t(uint32_t* r, uint32_t addr) {
    asm volatile("ldmatrix.sync.aligned.m8n8.x4.trans.shared.b16 {%0,%1,%2,%3}, [%4];"
                 : "=r"(r[0]), "=r"(r[1]), "=r"(r[2]), "=r"(r[3]) : "r"(addr));
}

__device__ __forceinline__ void mma16816(float* d, const uint32_t* a,
                                         uint32_t b0, uint32_t b1) {
    asm volatile(
        "mma.sync.aligned.m16n8k16.row.col.f32.f16.f16.f32 "
        "{%0,%1,%2,%3}, {%4,%5,%6,%7}, {%8,%9}, {%0,%1,%2,%3};"
        : "+f"(d[0]), "+f"(d[1]), "+f"(d[2]), "+f"(d[3])
        : "r"(a[0]), "r"(a[1]), "r"(a[2]), "r"(a[3]), "r"(b0), "r"(b1));
}

__device__ __forceinline__ uint32_t h2u(__half2 h) {
    return *reinterpret_cast<uint32_t*>(&h);
}

// ---------------- fp32 -> fp16 convert for all 5 tensors, one launch --------
__global__ void cvt5(const float* __restrict__ x,  const float* __restrict__ wq,
                     const float* __restrict__ wk, const float* __restrict__ wv,
                     const float* __restrict__ wo,
                     __half* __restrict__ xh, __half* __restrict__ wqh,
                     __half* __restrict__ wkh, __half* __restrict__ wvh,
                     __half* __restrict__ woh)
{
    long i = (long)(blockIdx.x * blockDim.x + threadIdx.x) * 4;
    const float* s; __half* d; long off;
    if (i < NXE)                              { s = x;  d = xh;  off = i; }
    else if ((off = i - NXE) < NQE)           { s = wq; d = wqh; }
    else if ((off = i - NXE - NQE) < NKE)     { s = wk; d = wkh; }
    else if ((off = i - NXE - NQE - NKE) < NKE) { s = wv; d = wvh; }
    else {
        off = i - NXE - NQE - 2L * NKE;
        if (off >= NQE) return;
        s = wo; d = woh;
    }
    float4 v = *(const float4*)(s + off);
    __half2 a = __floats2half2_rn(v.x, v.y);
    __half2 b = __floats2half2_rn(v.z, v.w);
    uint2 u = make_uint2(h2u(a), h2u(b));
    *(uint2*)(d + off) = u;
}

// ============ tensor-core GEMM core: acc += A[128,K] * B[128,K]^T ===========
#define GSTRIDE 144
#define PLANE_B (128 * GSTRIDE)     // 18432 B
#define STAGE_B (2 * PLANE_B)       // A + B
#define GEMM_SMEM (2 * STAGE_B)     // 73728 B

__device__ __forceinline__ void gemm_core(const __half* __restrict__ A,
                                          const __half* __restrict__ B,
                                          int K, int m0, int n0, char* sm,
                                          float (&acc)[2][8][4])
{
    const uint32_t sb = smem_u32(sm);
    const int tid = threadIdx.x;
    const int wid = tid >> 5;
    const int lane = tid & 31;
    const int warp_m = wid & 3;
    const int warp_n = wid >> 2;

#pragma unroll
    for (int a = 0; a < 2; a++)
#pragma unroll
        for (int b = 0; b < 8; b++)
#pragma unroll
            for (int c = 0; c < 4; c++) acc[a][b][c] = 0.f;

    auto stage = [&](int buf, int k0) {
        uint32_t dbase = sb + buf * STAGE_B;
#pragma unroll
        for (int it = 0; it < 4; it++) {
            int l = tid + it * 256;
            int row = l >> 3;
            int grp = l & 7;
            CP16(dbase + row * GSTRIDE + grp * 16,
                 A + (size_t)(m0 + row) * K + k0 + grp * 8);
            CP16(dbase + PLANE_B + row * GSTRIDE + grp * 16,
                 B + (size_t)(n0 + row) * K + k0 + grp * 8);
        }
    };

    const uint32_t loff =
        ((lane & 7) + ((lane >> 3) & 1) * 8) * GSTRIDE + (lane >> 4) * 16;

    auto compute = [&](int buf) {
        uint32_t base = sb + buf * STAGE_B;
        uint32_t aA = base + (warp_m * 32) * GSTRIDE + loff;
        uint32_t aB = base + PLANE_B + (warp_n * 64) * GSTRIDE + loff;
#pragma unroll
        for (int ks = 0; ks < 4; ks++) {
            uint32_t ck = ks * 32;
            uint32_t ah[2][4], bb[4][4];
            ldsm4(ah[0], aA + ck);
            ldsm4(ah[1], aA + 16 * GSTRIDE + ck);
#pragma unroll
            for (int g = 0; g < 4; g++)
                ldsm4(bb[g], aB + g * 16 * GSTRIDE + ck);
#pragma unroll
            for (int mt = 0; mt < 2; mt++)
#pragma unroll
                for (int nt = 0; nt < 8; nt++)
                    mma16816(acc[mt][nt], ah[mt],
                             bb[nt >> 1][nt & 1], bb[nt >> 1][2 + (nt & 1)]);
        }
    };

    stage(0, 0);
    CP_COMMIT();
    const int nch = K >> 6;
    int buf = 0;
    for (int ci = 0; ci < nch; ci++) {
        if (ci + 1 < nch) {
            stage(buf ^ 1, (ci + 1) << 6);
            CP_COMMIT();
            CP_WAIT1();
        } else {
            CP_WAIT0();
        }
        __syncthreads();
        compute(buf);
        __syncthreads();
        buf ^= 1;
    }
}

// fp32 epilogue (final output projection)
__device__ __forceinline__ void epi_plain_f(float (&acc)[2][8][4],
                                            const float* __restrict__ bias,
                                            float* __restrict__ C, int N,
                                            int m0, int n0)
{
    const int tid = threadIdx.x;
    const int wid = tid >> 5;
    const int lane = tid & 31;
    const int warp_m = wid & 3;
    const int warp_n = wid >> 2;
#pragma unroll
    for (int mt = 0; mt < 2; mt++) {
        int row = m0 + warp_m * 32 + mt * 16 + (lane >> 2);
#pragma unroll
        for (int nt = 0; nt < 8; nt++) {
            int col = n0 + warp_n * 64 + nt * 8 + (lane & 3) * 2;
            float2 bv = *(const float2*)&bias[col];
            *(float2*)&C[(size_t)row * N + col] =
                make_float2(acc[mt][nt][0] + bv.x, acc[mt][nt][1] + bv.y);
            *(float2*)&C[(size_t)(row + 8) * N + col] =
                make_float2(acc[mt][nt][2] + bv.x, acc[mt][nt][3] + bv.y);
        }
    }
}

// fp16 epilogue (V projection)
__device__ __forceinline__ void epi_plain_h(float (&acc)[2][8][4],
                                            const float* __restrict__ bias,
                                            __half* __restrict__ C, int N,
                                            int m0, int n0)
{
    const int tid = threadIdx.x;
    const int wid = tid >> 5;
    const int lane = tid & 31;
    const int warp_m = wid & 3;
    const int warp_n = wid >> 2;
#pragma unroll
    for (int mt = 0; mt < 2; mt++) {
        int row = m0 + warp_m * 32 + mt * 16 + (lane >> 2);
#pragma unroll
        for (int nt = 0; nt < 8; nt++) {
            int col = n0 + warp_n * 64 + nt * 8 + (lane & 3) * 2;
            float2 bv = *(const float2*)&bias[col];
            *(__half2*)&C[(size_t)row * N + col] =
                __floats2half2_rn(acc[mt][nt][0] + bv.x, acc[mt][nt][1] + bv.y);
            *(__half2*)&C[(size_t)(row + 8) * N + col] =
                __floats2half2_rn(acc[mt][nt][2] + bv.x, acc[mt][nt][3] + bv.y);
        }
    }
}

// fp16 rope epilogue (Q, K): + bias, YaRN rope in fp32, store fp16
__device__ __forceinline__ void epi_rope_h(float (&acc)[2][8][4],
                                           const float* __restrict__ bias,
                                           __half* __restrict__ C, int N,
                                           int m0, int n0,
                                           const int* __restrict__ pos)
{
    const int tid = threadIdx.x;
    const int wid = tid >> 5;
    const int lane = tid & 31;
    const int warp_m = wid & 3;
    const int warp_n = wid >> 2;

    int rbase = m0 + warp_m * 32 + (lane >> 2);
    float posr[4];
    posr[0] = (float)pos[rbase];
    posr[1] = (float)pos[rbase + 8];
    posr[2] = (float)pos[rbase + 16];
    posr[3] = (float)pos[rbase + 24];

    const float conc = 1.1386294361119891f;
#pragma unroll
    for (int nt = 0; nt < 4; nt++) {
        int i0 = nt * 8 + (lane & 3) * 2;
        float fr0 = expf(-(float)i0 * 0.2878231366242557f);
        float fr1 = expf(-(float)(i0 + 1) * 0.2878231366242557f);
        float wl0 = 6.283185307179586f / fr0;
        float wl1 = 6.283185307179586f / fr1;
        float t0 = fminf(fmaxf((wl0 - 32.0f) * (1.0f / 992.0f), 0.f), 1.f);
        float t1 = fminf(fmaxf((wl1 - 32.0f) * (1.0f / 992.0f), 0.f), 1.f);
        float e0 = fr0 * (1.0f - 0.75f * t0) * conc;
        float e1 = fr1 * (1.0f - 0.75f * t1) * conc;

        int c0 = n0 + warp_n * 64 + i0;
        float2 b1 = *(const float2*)&bias[c0];
        float2 b2 = *(const float2*)&bias[c0 + 32];
#pragma unroll
        for (int mt = 0; mt < 2; mt++)
#pragma unroll
            for (int sub = 0; sub < 2; sub++) {
                int row = m0 + warp_m * 32 + mt * 16 + (lane >> 2) + sub * 8;
                float p = posr[mt * 2 + sub];
                float s0, cs0, s1, cs1;
                sincosf(p * e0, &s0, &cs0);
                sincosf(p * e1, &s1, &cs1);
                float x1a = acc[mt][nt][sub * 2 + 0] + b1.x;
                float x1b = acc[mt][nt][sub * 2 + 1] + b1.y;
                float x2a = acc[mt][nt + 4][sub * 2 + 0] + b2.x;
                float x2b = acc[mt][nt + 4][sub * 2 + 1] + b2.y;
                *(__half2*)&C[(size_t)row * N + c0] =
                    __floats2half2_rn(x1a * cs0 - x2a * s0, x1b * cs1 - x2b * s1);
                *(__half2*)&C[(size_t)row * N + c0 + 32] =
                    __floats2half2_rn(x2a * cs0 + x1a * s0, x2b * cs1 + x1b * s1);
            }
    }
}

// merged Q/K/V projection (+ fused rope on Q,K). grid (24, 32)
__global__ __launch_bounds__(256, 2)
void gemm_qkv(const __half* __restrict__ A,
              const __half* __restrict__ Bq, const __half* __restrict__ Bk,
              const __half* __restrict__ Bv,
              const float* __restrict__ bq, const float* __restrict__ bk,
              const float* __restrict__ bv,
              __half* __restrict__ Cq, __half* __restrict__ Ck,
              __half* __restrict__ Cv, const int* __restrict__ pos)
{
    extern __shared__ char sm[];
    const int bx = blockIdx.x;
    const int m0 = blockIdx.y * 128;
    const __half* B; const float* bias; __half* C; int N, n0; bool rope = true;
    if (bx < 16)      { B = Bq; bias = bq; C = Cq; N = 2048; n0 = bx << 7; }
    else if (bx < 20) { B = Bk; bias = bk; C = Ck; N = 512; n0 = (bx - 16) << 7; }
    else              { B = Bv; bias = bv; C = Cv; N = 512; n0 = (bx - 20) << 7; rope = false; }

    float acc[2][8][4];
    gemm_core(A, B, EMB, m0, n0, sm, acc);
    if (rope) epi_rope_h(acc, bias, C, N, m0, n0, pos);
    else      epi_plain_h(acc, bias, C, N, m0, n0);
}

// output projection. grid (16, 32)
__global__ __launch_bounds__(256, 2)
void gemm_o(const __half* __restrict__ A, const __half* __restrict__ B,
            const float* __restrict__ bias, float* __restrict__ C)
{
    extern __shared__ char sm[];
    const int m0 = blockIdx.y * 128;
    const int n0 = blockIdx.x * 128;
    float acc[2][8][4];
    gemm_core(A, B, EMB, m0, n0, sm, acc);
    epi_plain_f(acc, bias, C, EMB, m0, n0);
}

// ============== tensor-core sliding-window flash attention ==================
// grid (32, 32, 2), 128 threads (4 warps x 16 q-rows). 64-query tiles,
// 64-key tiles (<=3), fp16 MMA, online softmax on fragments, sink in epilogue.
#define ASTRIDE 144

__global__ __launch_bounds__(128)
void attn_tc(const __half* __restrict__ Qh, const __half* __restrict__ Kh,
             const __half* __restrict__ Vh, const float* __restrict__ sinks,
             __half* __restrict__ ctx)
{
    __shared__ __align__(16) char sQ[64 * ASTRIDE];
    __shared__ __align__(16) char sK[2][64 * ASTRIDE];
    __shared__ __align__(16) char sV[2][64 * ASTRIDE];

    const int b = blockIdx.z;
    const int h = blockIdx.y;
    const int q0 = blockIdx.x * 64;
    const int kvh = h >> 2;
    const int tid = threadIdx.x;
    const int lane = tid & 31;
    const int wid = tid >> 5;          // warp -> 16 q-rows
    const uint32_t bQ = smem_u32(sQ);
    const uint32_t bK = smem_u32(sK);
    const uint32_t bV = smem_u32(sV);

    // Q tile load (64 rows x 128B)
#pragma unroll
    for (int it = 0; it < 4; it++) {
        int l = tid + it * 128;
        int row = l >> 3, grp = l & 7;
        CP16(bQ + row * ASTRIDE + grp * 16,
             Qh + (size_t)(b * S_LEN + q0 + row) * 2048 + h * 64 + grp * 8);
    }

    auto loadKV = [&](int buf, int kts) {
#pragma unroll
        for (int it = 0; it < 4; it++) {
            int l = tid + it * 128;
            int row = l >> 3, grp = l & 7;
            size_t g = (size_t)(b * S_LEN + kts + row) * 512 + kvh * 64 + grp * 8;
            CP16(bK + buf * 64 * ASTRIDE + row * ASTRIDE + grp * 16, Kh + g);
            CP16(bV + buf * 64 * ASTRIDE + row * ASTRIDE + grp * 16, Vh + g);
        }
    };

    const int kt_begin = (q0 >= WIN) ? (q0 - WIN) : 0;
    loadKV(0, kt_begin);
    CP_COMMIT();
    CP_WAIT0();
    __syncthreads();

    const uint32_t loff =
        ((lane & 7) + ((lane >> 3) & 1) * 8) * ASTRIDE + (lane >> 4) * 16;

    // Q fragments (A-layout), warp's 16 rows
    uint32_t aq[4][4];
    {
        uint32_t qb = bQ + (wid * 16) * ASTRIDE + loff;
#pragma unroll
        for (int ks = 0; ks < 4; ks++) ldsm4(aq[ks], qb + ks * 32);
    }

    const int i_lo = q0 + wid * 16 + (lane >> 2);
    const int i_hi = i_lo + 8;
    float m_lo = -1e4f, m_hi = -1e4f, l_lo = 0.f, l_hi = 0.f;
    float acc_o[8][4];
#pragma unroll
    for (int nt = 0; nt < 8; nt++)
#pragma unroll
        for (int c = 0; c < 4; c++) acc_o[nt][c] = 0.f;

    int buf = 0;
    for (int kts = kt_begin; kts <= q0; kts += 64) {
        if (kts + 64 <= q0) { loadKV(buf ^ 1, kts + 64); CP_COMMIT(); }

        // ---- S = Q K^T ----
        float s[8][4];
#pragma unroll
        for (int nt = 0; nt < 8; nt++)
#pragma unroll
            for (int c = 0; c < 4; c++) s[nt][c] = 0.f;
        uint32_t kb = bK + buf * 64 * ASTRIDE + loff;
#pragma unroll
        for (int ks = 0; ks < 4; ks++) {
            uint32_t bb[4][4];
#pragma unroll
            for (int g = 0; g < 4; g++)
                ldsm4(bb[g], kb + g * 16 * ASTRIDE + ks * 32);
#pragma unroll
            for (int nt = 0; nt < 8; nt++)
                mma16816(s[nt], aq[ks],
                         bb[nt >> 1][nt & 1], bb[nt >> 1][2 + (nt & 1)]);
        }

        // ---- mask + scale + row max ----
        float rmax_lo = -3e4f, rmax_hi = -3e4f;
#pragma unroll
        for (int nt = 0; nt < 8; nt++) {
            int j0 = kts + nt * 8 + 2 * (lane & 3);
            int j1 = j0 + 1;
            s[nt][0] = (j0 <= i_lo && j0 > i_lo - WIN) ? s[nt][0] * 0.125f : -3e4f;
            s[nt][1] = (j1 <= i_lo && j1 > i_lo - WIN) ? s[nt][1] * 0.125f : -3e4f;
            s[nt][2] = (j0 <= i_hi && j0 > i_hi - WIN) ? s[nt][2] * 0.125f : -3e4f;
            s[nt][3] = (j1 <= i_hi && j1 > i_hi - WIN) ? s[nt][3] * 0.125f : -3e4f;
            rmax_lo = fmaxf(rmax_lo, fmaxf(s[nt][0], s[nt][1]));
            rmax_hi = fmaxf(rmax_hi, fmaxf(s[nt][2], s[nt][3]));
        }
        rmax_lo = fmaxf(rmax_lo, __shfl_xor_sync(0xffffffffu, rmax_lo, 1));
        rmax_lo = fmaxf(rmax_lo, __shfl_xor_sync(0xffffffffu, rmax_lo, 2));
        rmax_hi = fmaxf(rmax_hi, __shfl_xor_sync(0xffffffffu, rmax_hi, 1));
        rmax_hi = fmaxf(rmax_hi, __shfl_xor_sync(0xffffffffu, rmax_hi, 2));

        float mn_lo = fmaxf(m_lo, rmax_lo);
        float mn_hi = fmaxf(m_hi, rmax_hi);
        float c_lo = __expf(m_lo - mn_lo);
        float c_hi = __expf(m_hi - mn_hi);
        m_lo = mn_lo; m_hi = mn_hi;
        l_lo *= c_lo; l_hi *= c_hi;
#pragma unroll
        for (int nt = 0; nt < 8; nt++) {
            acc_o[nt][0] *= c_lo; acc_o[nt][1] *= c_lo;
            acc_o[nt][2] *= c_hi; acc_o[nt][3] *= c_hi;
        }

        // ---- P = exp(s - m), pack to fp16 A-fragments ----
        uint32_t ap[4][4];
#pragma unroll
        for (int nt = 0; nt < 8; nt++) {
            float p0 = __expf(s[nt][0] - m_lo);
            float p1 = __expf(s[nt][1] - m_lo);
            float p2 = __expf(s[nt][2] - m_hi);
            float p3 = __expf(s[nt][3] - m_hi);
            l_lo += p0 + p1;
            l_hi += p2 + p3;
            int kt = nt >> 1;
            uint32_t u01 = h2u(__floats2half2_rn(p0, p1));
            uint32_t u23 = h2u(__floats2half2_rn(p2, p3));
            if ((nt & 1) == 0) { ap[kt][0] = u01; ap[kt][1] = u23; }
            else               { ap[kt][2] = u01; ap[kt][3] = u23; }
        }

        // ---- O += P V  (V via ldmatrix.trans) ----
        uint32_t vb0 = bV + buf * 64 * ASTRIDE + loff;
#pragma unroll
        for (int kt = 0; kt < 4; kt++) {
#pragma unroll
            for (int nbi = 0; nbi < 4; nbi++) {
                uint32_t vb[4];
                ldsm4t(vb, vb0 + kt * 16 * ASTRIDE + nbi * 32);
                mma16816(acc_o[nbi * 2],     ap[kt], vb[0], vb[1]);
                mma16816(acc_o[nbi * 2 + 1], ap[kt], vb[2], vb[3]);
            }
        }

        if (kts + 64 <= q0) CP_WAIT0();
        __syncthreads();
        buf ^= 1;
    }

    // ---- epilogue: reduce l, merge sink, normalize, store fp16 ctx ----
    l_lo += __shfl_xor_sync(0xffffffffu, l_lo, 1);
    l_lo += __shfl_xor_sync(0xffffffffu, l_lo, 2);
    l_hi += __shfl_xor_sync(0xffffffffu, l_hi, 1);
    l_hi += __shfl_xor_sync(0xffffffffu, l_hi, 2);

    float snk = sinks[h];
    float mf_lo = fmaxf(m_lo, snk);
    float mf_hi = fmaxf(m_hi, snk);
    float e_lo = __expf(m_lo - mf_lo);
    float e_hi = __expf(m_hi - mf_hi);
    float f_lo = e_lo / (l_lo * e_lo + __expf(snk - mf_lo));
    float f_hi = e_hi / (l_hi * e_hi + __expf(snk - mf_hi));

    size_t base_lo = (size_t)(b * S_LEN + i_lo) * 2048 + h * 64;
    size_t base_hi = (size_t)(b * S_LEN + i_hi) * 2048 + h * 64;
#pragma unroll
    for (int nt = 0; nt < 8; nt++) {
        int col = nt * 8 + 2 * (lane & 3);
        *(__half2*)&ctx[base_lo + col] =
            __floats2half2_rn(acc_o[nt][0] * f_lo, acc_o[nt][1] * f_lo);
        *(__half2*)&ctx[base_hi + col] =
            __floats2half2_rn(acc_o[nt][2] * f_hi, acc_o[nt][3] * f_hi);
    }
}

// ---------------- launch -----------------------------------------------------
extern "C" void kernel_launch(void* const* d_in, const int* in_sizes, int n_in,
                              void* d_out, int out_size)
{
    const float* x     = (const float*)d_in[0];
    const float* Wq    = (const float*)d_in[1];
    const float* bq    = (const float*)d_in[2];
    const float* Wk    = (const float*)d_in[3];
    const float* bk    = (const float*)d_in[4];
    const float* Wv    = (const float*)d_in[5];
    const float* bv    = (const float*)d_in[6];
    const float* Wo    = (const float*)d_in[7];
    const float* bo    = (const float*)d_in[8];
    const float* sinks = (const float*)d_in[9];
    const int*   pos   = (const int*)d_in[10];
    float* out = (float*)d_out;

    __half *gQ, *gK, *gV, *xh, *qh, *kh, *vh, *oh, *ch;
    cudaGetSymbolAddress((void**)&gQ, g_Qa);
    cudaGetSymbolAddress((void**)&gK, g_Ka);
    cudaGetSymbolAddress((void**)&gV, g_Va);
    cudaGetSymbolAddress((void**)&xh, g_xh);
    cudaGetSymbolAddress((void**)&qh, g_Wqh);
    cudaGetSymbolAddress((void**)&kh, g_Wkh);
    cudaGetSymbolAddress((void**)&vh, g_Wvh);
    cudaGetSymbolAddress((void**)&oh, g_Woh);
    cudaGetSymbolAddress((void**)&ch, g_ch);

    cudaFuncSetAttribute(gemm_qkv, cudaFuncAttributeMaxDynamicSharedMemorySize,
                         GEMM_SMEM);
    cudaFuncSetAttribute(gemm_o, cudaFuncAttributeMaxDynamicSharedMemorySize,
                         GEMM_SMEM);

    // fp16 conversion of x and all weights, one launch
    int total4 = (NXE + 2 * NQE + 2 * NKE) / 4;
    cvt5<<<(total4 + 255) / 256, 256>>>(x, Wq, Wk, Wv, Wo, xh, qh, kh, vh, oh);

    // Q/K/V projections + fused YaRN rope (Q,K), fp16 outputs
    gemm_qkv<<<dim3(24, 32), 256, GEMM_SMEM>>>(xh, qh, kh, vh, bq, bk, bv,
                                               gQ, gK, gV, pos);

    // tensor-core windowed attention with sink -> ctx fp16
    attn_tc<<<dim3(S_LEN / 64, NH, BATCH), 128>>>(gQ, gK, gV, sinks, ch);

    // output projection
    gemm_o<<<dim3(16, 32), 256, GEMM_SMEM>>>(ch, oh, bo, out);
}